// round 9
// baseline (speedup 1.0000x reference)
#include <cuda_runtime.h>

#define TT 1024
#define BBATCH 32
#define DD 1024
#define GCTA 128
#define NTH 256

typedef unsigned long long u64;

__device__ float g_Y[(size_t)TT * BBATCH * 3072];      // ax|bx|wx interleaved
__device__ float g_H[(size_t)(TT + 1) * BBATCH * DD];  // fallback h chain
__device__ unsigned g_count;
__device__ unsigned g_release;

__device__ __forceinline__ u64 pk2(float x, float y) {
    u64 r;
    asm("mov.b64 %0, {%1, %2};" : "=l"(r) : "f"(x), "f"(y));
    return r;
}
__device__ __forceinline__ void fma2(u64& d, u64 a, u64 b) {
    asm("fma.rn.f32x2 %0, %1, %2, %0;" : "+l"(d) : "l"(a), "l"(b));
}
__device__ __forceinline__ void up2(u64 v, float& x, float& y) {
    asm("mov.b64 {%0, %1}, %2;" : "=f"(x), "=f"(y) : "l"(v));
}
__device__ __forceinline__ float sgm(float z) {
    return __fdividef(1.0f, 1.0f + __expf(-z));
}
__device__ __forceinline__ float tnh(float z) {
    return __fdividef(2.0f, 1.0f + __expf(-2.0f * z)) - 1.0f;
}

__global__ void reset_kernel(float* __restrict__ hbase) {
    unsigned i = blockIdx.x * blockDim.x + threadIdx.x;  // 32768 = B*D
    hbase[i] = 0.0f;
    if (i == 0) { g_count = 0u; g_release = 0u; }
}

// Y[m][n] = sum_k X[m][k] * Wrow[n][k].  grid = (24, 256), 256 threads.
// As stored pre-duplicated (v,v) as u64; Bs read as adjacent u64 pairs:
// the f32x2 mainloop has ZERO packing MOVs.
__global__ void __launch_bounds__(256, 2) gemm_kernel(const float* __restrict__ X,
                                                      const float* __restrict__ Wa,
                                                      const float* __restrict__ Wb,
                                                      const float* __restrict__ Wx) {
    __shared__ __align__(16) u64 AsD[8][128];     // duplicated pairs, 8 KB
    __shared__ __align__(16) float Bs[8][128];    // 4 KB
    const int bn = blockIdx.x, bm = blockIdx.y, tid = threadIdx.x;
    const int tx = tid & 15, ty = tid >> 4;
    const float* Wsrc = (bn < 8) ? Wa : (bn < 16) ? Wb : Wx;
    const int nloc = (bn & 7) * 128;
    const int row = tid >> 1, cg = (tid & 1) * 4;

    u64 acc2[8][4];
#pragma unroll
    for (int i = 0; i < 8; ++i)
#pragma unroll
        for (int j = 0; j < 4; ++j) acc2[i][j] = 0ull;

    for (int k0 = 0; k0 < 1024; k0 += 8) {
        float4 a = *(const float4*)(X + (size_t)(bm * 128 + row) * 1024 + k0 + cg);
        float4 b = *(const float4*)(Wsrc + (size_t)(nloc + row) * 1024 + k0 + cg);
        AsD[cg + 0][row] = pk2(a.x, a.x);
        AsD[cg + 1][row] = pk2(a.y, a.y);
        AsD[cg + 2][row] = pk2(a.z, a.z);
        AsD[cg + 3][row] = pk2(a.w, a.w);
        Bs[cg + 0][row] = b.x; Bs[cg + 1][row] = b.y;
        Bs[cg + 2][row] = b.z; Bs[cg + 3][row] = b.w;
        __syncthreads();
#pragma unroll
        for (int kk = 0; kk < 8; ++kk) {
            u64 av[8];
#pragma unroll
            for (int i = 0; i < 8; ++i) av[i] = AsD[kk][ty * 8 + i];
            ulonglong2 b0 = *(const ulonglong2*)&Bs[kk][tx * 8];
            ulonglong2 b1 = *(const ulonglong2*)&Bs[kk][tx * 8 + 4];
            u64 bd[4] = {b0.x, b0.y, b1.x, b1.y};
#pragma unroll
            for (int i = 0; i < 8; ++i)
#pragma unroll
                for (int j = 0; j < 4; ++j) fma2(acc2[i][j], av[i], bd[j]);
        }
        __syncthreads();
    }
#pragma unroll
    for (int i = 0; i < 8; ++i) {
        float o[8];
#pragma unroll
        for (int j = 0; j < 4; ++j) up2(acc2[i][j], o[2 * j], o[2 * j + 1]);
        size_t m = (size_t)bm * 128 + ty * 8 + i;
        float* dst = g_Y + m * 3072 + bn * 128 + tx * 8;
        *(float4*)dst = make_float4(o[0], o[1], o[2], o[3]);
        *(float4*)(dst + 4) = make_float4(o[4], o[5], o[6], o[7]);
    }
}

// Persistent recurrence. CTA owns features [e0, e0+8) of Ua/Ub/Wh (96 KB SMEM).
// h and w consumed as u64 pairs directly -> no packing MOVs in the dot loop.
__global__ void __launch_bounds__(NTH, 1) recur_kernel(
    const float* __restrict__ Ua, const float* __restrict__ Ub,
    const float* __restrict__ Wh, const float* __restrict__ p_ba,
    const float* __restrict__ p_bb, const float* __restrict__ p_bv,
    float* __restrict__ outp, float* __restrict__ hbase) {
    extern __shared__ ulonglong2 ws2[];  // 24 rows * 256 * 16B = 96 KB
    __shared__ float Psm[32][24];        // [batch][row]

    const int tid = threadIdx.x;
    const int lane = tid & 31, wid = tid >> 5;
    const int e0 = blockIdx.x * 8;

    for (int idx = tid; idx < 24 * 256; idx += NTH) {
        int r = idx >> 8, c = idx & 255;
        const float* src = (r < 8) ? Ua + (size_t)(e0 + r) * DD
                         : (r < 16) ? Ub + (size_t)(e0 + r - 8) * DD
                                    : Wh + (size_t)(e0 + r - 16) * DD;
        ws2[idx] = ((const ulonglong2*)src)[c];
    }
    const int eb = tid & 7;   // epilogue feature
    const int bi = tid >> 3;  // epilogue batch
    const float rba = p_ba[e0 + eb];
    const float rbb = p_bb[e0 + eb];
    const float rbv = p_bv[e0 + eb];
    __syncthreads();

#pragma unroll 1
    for (int t = 0; t < TT; ++t) {
        const float* hp = hbase + (size_t)t * (BBATCH * DD);

        // Prefetch epilogue operands early (hidden under the row loop).
        size_t ybase = ((size_t)t * BBATCH + bi) * 3072 + e0 + eb;
        float ya = g_Y[ybase];
        float yb = g_Y[ybase + 1024];
        float yv = g_Y[ybase + 2048];
        float hv = hp[(size_t)bi * DD + e0 + eb];

        // h: 4 batches x 16 u64 pairs/lane (interleaved, coalesced LDG.128)
        ulonglong2 hu[4][8];
#pragma unroll
        for (int b4 = 0; b4 < 4; ++b4) {
            const ulonglong2* hb =
                (const ulonglong2*)(hp + (size_t)(wid * 4 + b4) * DD + lane * 4);
#pragma unroll
            for (int i = 0; i < 8; ++i) hu[b4][i] = hb[i * 32];
        }

#pragma unroll 1
        for (int r = 0; r < 24; ++r) {
            ulonglong2 w2[8];
#pragma unroll
            for (int i = 0; i < 8; ++i) w2[i] = ws2[r * 256 + lane + 32 * i];
#pragma unroll
            for (int b4 = 0; b4 < 4; ++b4) {
                u64 a01 = 0ull, a23 = 0ull;
#pragma unroll
                for (int i = 0; i < 8; ++i) {
                    fma2(a01, hu[b4][i].x, w2[i].x);
                    fma2(a23, hu[b4][i].y, w2[i].y);
                }
                float p0, p1, q0, q1;
                up2(a01, p0, p1);
                up2(a23, q0, q1);
                float s = (p0 + p1) + (q0 + q1);
#pragma unroll
                for (int off = 16; off; off >>= 1)
                    s += __shfl_xor_sync(0xffffffffu, s, off);
                if (lane == 0) Psm[wid * 4 + b4][r] = s;
            }
        }
        __syncthreads();

        {   // fused gate epilogue: thread -> (batch bi, feature e0+eb)
            float pa = Psm[bi][eb] + ya + rba;
            float pb = Psm[bi][8 + eb] + yb + rbb;
            float pv = Psm[bi][16 + eb] + yv + rbv;
            float al = sgm(pa);
            float be = sgm(pb);
            float v = tnh(pv);
            float hn = al * hv + be * v;
            float o = hn * hn * sgm(hn);  // h * silu(h)
            size_t oidx = (size_t)t * (BBATCH * DD) + (size_t)bi * DD + e0 + eb;
            outp[oidx] = o;
            hbase[oidx + BBATCH * DD] = hn;  // h[t+1]
        }
        if (t == TT - 1) break;

        // Grid barrier: syncthreads, then tid0-only release/acquire fencing.
        __syncthreads();
        if (tid == 0) {
            __threadfence();
            unsigned arrived = atomicAdd(&g_count, 1u) + 1u;
            unsigned want = (unsigned)(t + 1) * (unsigned)GCTA;
            if (arrived == want) atomicExch(&g_release, (unsigned)(t + 1));
            while (*((volatile unsigned*)&g_release) < (unsigned)(t + 1))
                __nanosleep(32);
            __threadfence();
        }
        __syncthreads();
    }
}

extern "C" void kernel_launch(void* const* d_in, const int* in_sizes, int n_in,
                              void* d_out, int out_size) {
    (void)in_sizes; (void)n_in;
    const float* x  = (const float*)d_in[0];
    const float* Wa = (const float*)d_in[1];
    const float* Ua = (const float*)d_in[2];
    const float* ba = (const float*)d_in[3];
    const float* Wb = (const float*)d_in[4];
    const float* Ub = (const float*)d_in[5];
    const float* bb = (const float*)d_in[6];
    const float* Wh = (const float*)d_in[7];
    const float* Wx = (const float*)d_in[8];
    const float* bv = (const float*)d_in[9];
    float* outp = (float*)d_out;

    // Output may be outputs(T,B,D) ++ h(T+1,B,D), or outputs only.
    const long long need =
        (long long)TT * BBATCH * DD + (long long)(TT + 1) * BBATCH * DD;
    float* hbase;
    if ((long long)out_size >= need) {
        hbase = outp + (size_t)TT * BBATCH * DD;
    } else {
        void* p = nullptr;
        cudaGetSymbolAddress(&p, g_H);
        hbase = (float*)p;
    }

    cudaFuncSetAttribute(recur_kernel,
                         cudaFuncAttributeMaxDynamicSharedMemorySize, 98304);

    reset_kernel<<<128, 256>>>(hbase);
    dim3 gg(24, 256);
    gemm_kernel<<<gg, 256>>>(x, Wa, Wb, Wx);
    recur_kernel<<<GCTA, NTH, 98304>>>(Ua, Ub, Wh, ba, bb, bv, outp, hbase);
}